// round 9
// baseline (speedup 1.0000x reference)
#include <cuda_runtime.h>
#include <cuda_bf16.h>

// Problem constants (GNHP_32796370273029)
#define BB      128      // batch
#define TP2     2050     // T+2
#define TS      2049     // scan steps
#define HH      64       // hidden
#define GG      448      // 7*H gates
#define KK      100      // num event types (output)
#define NE      103      // K+3 embedding rows
#define NTH     640      // scan threads: 448 gate + 128 logits + 64 update

typedef unsigned long long ull;

// ---------------- packed f32x2 helpers ----------------
__device__ __forceinline__ ull pack2(float lo, float hi) {
    ull r; asm("mov.b64 %0, {%1, %2};" : "=l"(r) : "f"(lo), "f"(hi)); return r;
}
__device__ __forceinline__ void unpack2(ull v, float& lo, float& hi) {
    asm("mov.b64 {%0, %1}, %2;" : "=f"(lo), "=f"(hi) : "l"(v));
}
__device__ __forceinline__ void fma2(ull& d, ull a, ull b) {
    asm("fma.rn.f32x2 %0, %1, %2, %0;" : "+l"(d) : "l"(a), "l"(b));
}
__device__ __forceinline__ ull add2(ull a, ull b) {
    ull r; asm("add.rn.f32x2 %0, %1, %2;" : "=l"(r) : "l"(a), "l"(b)); return r;
}

// ---------------- raw MUFU wrappers ----------------
__device__ __forceinline__ float ex2f(float x) {
    float r; asm("ex2.approx.f32 %0, %1;" : "=f"(r) : "f"(x)); return r;
}
__device__ __forceinline__ float rcpf(float x) {
    float r; asm("rcp.approx.f32 %0, %1;" : "=f"(r) : "f"(x)); return r;
}
__device__ __forceinline__ float lg2f(float x) {
    float r; asm("lg2.approx.f32 %0, %1;" : "=f"(r) : "f"(x)); return r;
}

#define L2E 1.4426950408889634f
#define LN2 0.6931471805599453f

// Unified gate nonlinearity. type: 0,1,3,4,5=sigmoid  2=tanh  6=softplus.
// type is warp-uniform (warp w handles gates [32w,32w+32) -> type w/2).
__device__ __forceinline__ float act(float g, int type) {
    float a = (type == 2) ? (2.0f * L2E) : ((type == 6) ? L2E : -L2E);
    float t = ex2f(g * a);            // e^{2g} | e^{g} | e^{-g}
    float u = 1.0f + t;
    float r = rcpf(u);
    float res = (type == 2) ? fmaf(-2.0f, r, 1.0f) : r;
    if (type == 6) {
        float sp = lg2f(u) * LN2;
        res = (g > 80.0f) ? g : sp;
    }
    return res;
}

__device__ __forceinline__ float softplus_f(float x) {
    return fmaxf(x, 0.0f) + __logf(1.0f + __expf(-fabsf(x)));
}

// ---------------- scratch (device globals — no allocs allowed) ----------------
__device__ float g_P[NE * GG];                 // precomputed in_emb@Wx + b

// ============================================================
// Kernel 1: precompute P = in_emb @ Wx + b
// ============================================================
__global__ void prep_kernel(const float* __restrict__ in_emb,
                            const float* __restrict__ Wx,
                            const float* __restrict__ bias) {
    int j = threadIdx.x;
    int e = blockIdx.x;
    __shared__ float emb_s[HH];
    if (j < HH) emb_s[j] = in_emb[e * HH + j];
    __syncthreads();
    float acc = bias[j];
    #pragma unroll
    for (int k = 0; k < HH; k++)
        acc = fmaf(emb_s[k], Wx[k * GG + j], acc);
    g_P[e * GG + j] = acc;
}

// ============================================================
// Kernel 2: fused CT-LSTM scan + logits. One CTA per batch row, 640 threads.
//   warps  0-13 (tid   0-447): gate tid — Wh column in 32 ull regs, 32 fma2 dot
//   warps 14-17 (tid 448-575): logits col c=tid-448 (c<100) — out_emb in regs;
//                              dot runs in the post-BAR1 window on h(t-1)
//   warps 18-19 (tid 576-639): state update for dim d=tid-576 (top priority)
// h double-buffered: dot/logits read hb[t&1], update writes hb[(t+1)&1].
// ============================================================
__global__ __launch_bounds__(NTH, 1)
void scan_kernel(const int* __restrict__ ev,
                 const float* __restrict__ dts,
                 const float* __restrict__ Wh,
                 const float* __restrict__ out_emb,
                 float* __restrict__ out) {
    const int b   = blockIdx.x;
    const int tid = threadIdx.x;

    __shared__ __align__(16) float hb[2][HH];
    __shared__ float tg_sm[GG];
    __shared__ int   ev_sm[TS];
    __shared__ float ndt_sm[TS];      // -log2(e) * dt  (pre-scaled for ex2)

    for (int t = tid; t < TS; t += NTH) {
        ev_sm[t]  = ev[b * TP2 + t];             // event_tensor[:, :-1]
        ndt_sm[t] = -L2E * dts[b * TP2 + t + 1]; // dtime_tensor[:, 1:]
    }
    if (tid < HH) { hb[0][tid] = 0.0f; hb[1][tid] = 0.0f; }

    const bool is_gate   = (tid < GG);
    const bool is_logit  = (tid >= GG) && (tid < GG + 128);
    const bool is_update = (tid >= GG + 128);

    // per-role register state (loaded only where used)
    ull  w[32];                       // gate: Wh column; logit: out_emb row
    int  type = 0;
    if (is_gate) {
        #pragma unroll
        for (int k = 0; k < 32; k++)
            w[k] = pack2(Wh[(2 * k) * GG + tid], Wh[(2 * k + 1) * GG + tid]);
        type = tid >> 6;
    }
    const int  c      = tid - GG;               // logits column
    const bool cvalid = is_logit && (c < KK);
    if (is_logit) {
        const int cc = (c < KK) ? c : 0;
        const ull* oer = reinterpret_cast<const ull*>(out_emb + cc * HH);
        #pragma unroll
        for (int k = 0; k < 32; k++) w[k] = oer[k];
    }
    const int d = tid - (GG + 128);             // update dim
    float c_reg = 0.0f, cb_reg = 0.0f;

    __syncthreads();

    float pa = is_gate ? g_P[ev_sm[0] * GG + tid] : 0.0f;
    float* outb = out + (long)b * TS * KK;

    for (int t = 0; t < TS; t++) {
        const float* hcur  = hb[t & 1];
        float*       hnext = hb[(t + 1) & 1];

        if (is_gate) {
            // prefetch next step's pre-activation
            int e_next = (t + 1 < TS) ? ev_sm[t + 1] : 0;
            float pa_n = g_P[e_next * GG + tid];

            // 64-dot: 4 chains (depth 8), h via LDS.128
            ull a0 = pack2(pa, 0.0f), a1 = 0ULL, a2 = 0ULL, a3 = 0ULL;
            const ulonglong2* hp2 = reinterpret_cast<const ulonglong2*>(hcur);
            #pragma unroll
            for (int k = 0; k < 16; k += 2) {
                ulonglong2 p = hp2[k], q = hp2[k + 1];
                fma2(a0, p.x, w[2 * k]);     fma2(a1, p.y, w[2 * k + 1]);
                fma2(a2, q.x, w[2 * k + 2]); fma2(a3, q.y, w[2 * k + 3]);
            }
            ull s = add2(add2(a0, a1), add2(a2, a3));
            float lo, hi; unpack2(s, lo, hi);
            tg_sm[tid] = act(lo + hi, type);
            pa = pa_n;
        }
        __syncthreads();              // BAR1: gates ready

        if (is_logit) {
            // logits for h(t-1) = hcur (just consumed by the dot); t=0 -> h=0, skip
            if (t > 0 && cvalid) {
                ull o0 = 0ULL, o1 = 0ULL, o2 = 0ULL, o3 = 0ULL;
                const ulonglong2* hp2 = reinterpret_cast<const ulonglong2*>(hcur);
                #pragma unroll
                for (int k = 0; k < 16; k += 2) {
                    ulonglong2 p = hp2[k], q = hp2[k + 1];
                    fma2(o0, p.x, w[2 * k]);     fma2(o1, p.y, w[2 * k + 1]);
                    fma2(o2, q.x, w[2 * k + 2]); fma2(o3, q.y, w[2 * k + 3]);
                }
                ull s = add2(add2(o0, o1), add2(o2, o3));
                float lo, hi; unpack2(s, lo, hi);
                outb[(long)(t - 1) * KK + c] = softplus_f(lo + hi);
            }
        } else if (is_update) {
            float i_  = tg_sm[d];
            float f_  = tg_sm[64  + d];
            float z_  = tg_sm[128 + d];
            float o_  = tg_sm[192 + d];
            float ib_ = tg_sm[256 + d];
            float fb_ = tg_sm[320 + d];
            float dl_ = tg_sm[384 + d];
            float c_i  = fmaf(f_,  c_reg,  i_  * z_);
            float cb_i = fmaf(fb_, cb_reg, ib_ * z_);
            float edec = ex2f(dl_ * ndt_sm[t]);          // e^{-delta*dt}
            float c_n  = fmaf(c_i - cb_i, edec, cb_i);
            // tanh(c_n) = 1 - 2/(1+e^{2c})
            float tt = ex2f(c_n * (2.0f * L2E));
            float th = fmaf(-2.0f, rcpf(1.0f + tt), 1.0f);
            c_reg  = c_n;
            cb_reg = cb_i;
            hnext[d] = o_ * th;
        }
        __syncthreads();              // BAR2: h(t) ready
    }

    // epilogue: logits for the final hidden state h(TS-1), in hb[TS&1]
    if (cvalid) {
        const ulonglong2* hp2 = reinterpret_cast<const ulonglong2*>(hb[TS & 1]);
        ull o0 = 0ULL, o1 = 0ULL, o2 = 0ULL, o3 = 0ULL;
        #pragma unroll
        for (int k = 0; k < 16; k += 2) {
            ulonglong2 p = hp2[k], q = hp2[k + 1];
            fma2(o0, p.x, w[2 * k]);     fma2(o1, p.y, w[2 * k + 1]);
            fma2(o2, q.x, w[2 * k + 2]); fma2(o3, q.y, w[2 * k + 3]);
        }
        ull s = add2(add2(o0, o1), add2(o2, o3));
        float lo, hi; unpack2(s, lo, hi);
        outb[(long)(TS - 1) * KK + c] = softplus_f(lo + hi);
    }
}

// ============================================================
// Padding no-op (ncu sampling alignment attempt).
// ============================================================
__global__ void ncu_pad_kernel() {}

// ============================================================
extern "C" void kernel_launch(void* const* d_in, const int* in_sizes, int n_in,
                              void* d_out, int out_size) {
    const int*   ev      = (const int*)  d_in[0];
    const float* dts     = (const float*)d_in[1];
    const float* in_emb  = (const float*)d_in[2];
    const float* Wx      = (const float*)d_in[3];
    const float* Wh      = (const float*)d_in[4];
    const float* bias    = (const float*)d_in[5];
    const float* out_emb = (const float*)d_in[6];
    float* out = (float*)d_out;

    prep_kernel<<<NE, GG>>>(in_emb, Wx, bias);
    scan_kernel<<<BB, NTH>>>(ev, dts, Wh, out_emb, out);
    ncu_pad_kernel<<<1, 32>>>();
}

// round 10
// speedup vs baseline: 2.3684x; 2.3684x over previous
#include <cuda_runtime.h>
#include <cuda_bf16.h>

// Problem constants (GNHP_32796370273029)
#define BB      128      // batch
#define TP2     2050     // T+2
#define TS      2049     // scan steps
#define HH      64       // hidden
#define GG      448      // 7*H gates
#define KK      100      // num event types (output)
#define NE      103      // K+3 embedding rows
#define NT      224      // scan threads (2 gates per thread)

typedef unsigned long long ull;

// ---------------- packed f32x2 helpers ----------------
__device__ __forceinline__ ull pack2(float lo, float hi) {
    ull r; asm("mov.b64 %0, {%1, %2};" : "=l"(r) : "f"(lo), "f"(hi)); return r;
}
__device__ __forceinline__ void unpack2(ull v, float& lo, float& hi) {
    asm("mov.b64 {%0, %1}, %2;" : "=f"(lo), "=f"(hi) : "l"(v));
}
__device__ __forceinline__ void fma2(ull& d, ull a, ull b) {
    asm("fma.rn.f32x2 %0, %1, %2, %0;" : "+l"(d) : "l"(a), "l"(b));
}
__device__ __forceinline__ ull add2(ull a, ull b) {
    ull r; asm("add.rn.f32x2 %0, %1, %2;" : "=l"(r) : "l"(a), "l"(b)); return r;
}

// ---------------- raw MUFU wrappers ----------------
__device__ __forceinline__ float ex2f(float x) {
    float r; asm("ex2.approx.f32 %0, %1;" : "=f"(r) : "f"(x)); return r;
}
__device__ __forceinline__ float rcpf(float x) {
    float r; asm("rcp.approx.f32 %0, %1;" : "=f"(r) : "f"(x)); return r;
}
__device__ __forceinline__ float lg2f(float x) {
    float r; asm("lg2.approx.f32 %0, %1;" : "=f"(r) : "f"(x)); return r;
}
__device__ __forceinline__ float tanhf_hw(float x) {
    float r; asm("tanh.approx.f32 %0, %1;" : "=f"(r) : "f"(x)); return r;
}

#define L2E 1.4426950408889634f
#define LN2 0.6931471805599453f

// Unified gate nonlinearity. type: 0,1,3,4,5=sigmoid  2=tanh  6=softplus.
// Accurate ex2/rcp path (throughput-overlapped with the fma dot phase).
__device__ __forceinline__ float act(float g, int type) {
    float a = (type == 2) ? (2.0f * L2E) : ((type == 6) ? L2E : -L2E);
    float t = ex2f(g * a);            // e^{2g} | e^{g} | e^{-g}
    float u = 1.0f + t;
    float r = rcpf(u);
    float res = (type == 2) ? fmaf(-2.0f, r, 1.0f) : r;
    if (type == 6) {                  // warp-uniform (gates 384..447)
        float sp = lg2f(u) * LN2;
        res = (g > 80.0f) ? g : sp;
    }
    return res;
}

__device__ __forceinline__ float softplus_f(float x) {
    return fmaxf(x, 0.0f) + __logf(1.0f + __expf(-fabsf(x)));
}

// ---------------- scratch (device globals — no allocs allowed) ----------------
__device__ float g_P[NE * GG];                 // precomputed in_emb@Wx + b

// ============================================================
// Kernel 1: precompute P = in_emb @ Wx + b
// ============================================================
__global__ void prep_kernel(const float* __restrict__ in_emb,
                            const float* __restrict__ Wx,
                            const float* __restrict__ bias) {
    int j = threadIdx.x;
    int e = blockIdx.x;
    __shared__ float emb_s[HH];
    if (j < HH) emb_s[j] = in_emb[e * HH + j];
    __syncthreads();
    float acc = bias[j];
    #pragma unroll
    for (int k = 0; k < HH; k++)
        acc = fmaf(emb_s[k], Wx[k * GG + j], acc);
    g_P[e * GG + j] = acc;
}

// ============================================================
// Kernel 2: fused CT-LSTM scan + logits. One CTA per batch row, 224 threads.
//   All threads: gates tid and tid+224 (Wh column pairs in regs, 128 regs).
//   Post-BAR1 window:
//     warps 0-1 (tid 0-63):   state update for dim d=tid (tanh.approx tail)
//     tid 64-163:             logits col c=tid-64 on h(t-1)  (oe in 64 regs)
//   h double-buffered: dot/logits read hb[t&1], update writes hb[(t+1)&1].
// ============================================================
__global__ __launch_bounds__(NT, 1)
void scan_kernel(const int* __restrict__ ev,
                 const float* __restrict__ dts,
                 const float* __restrict__ Wh,
                 const float* __restrict__ out_emb,
                 float* __restrict__ out) {
    const int b   = blockIdx.x;
    const int tid = threadIdx.x;

    __shared__ __align__(16) float hb[2][HH];
    __shared__ float tg_sm[GG];
    __shared__ int   ev_sm[TS];
    __shared__ float ndt_sm[TS];      // -log2(e) * dt  (pre-scaled for ex2)

    for (int t = tid; t < TS; t += NT) {
        ev_sm[t]  = ev[b * TP2 + t];             // event_tensor[:, :-1]
        ndt_sm[t] = -L2E * dts[b * TP2 + t + 1]; // dtime_tensor[:, 1:]
    }
    if (tid < HH) { hb[0][tid] = 0.0f; hb[1][tid] = 0.0f; }

    // Wh column pairs for both gate slots, in registers.
    ull wa[32], wb[32];
    #pragma unroll
    for (int k = 0; k < 32; k++) {
        wa[k] = pack2(Wh[(2 * k) * GG + tid],      Wh[(2 * k + 1) * GG + tid]);
        wb[k] = pack2(Wh[(2 * k) * GG + tid + NT], Wh[(2 * k + 1) * GG + tid + NT]);
    }

    // logits column ownership: tid 64..163 -> col 0..99
    const int  c      = tid - 64;
    const bool cvalid = (c >= 0) && (c < KK);
    ull oe[32];
    {
        const int cc = cvalid ? c : 0;
        const ull* oer = reinterpret_cast<const ull*>(out_emb + cc * HH);
        #pragma unroll
        for (int k = 0; k < 32; k++) oe[k] = oer[k];
    }

    const int ta = tid >> 6;          // type of gate slot A (warp-uniform)
    const int tb = (tid + NT) >> 6;   // type of gate slot B (warp-uniform)
    const int d  = tid;               // update dim (tid < 64)

    float c_reg = 0.0f, cb_reg = 0.0f;

    __syncthreads();

    float pa = g_P[ev_sm[0] * GG + tid];
    float pb = g_P[ev_sm[0] * GG + tid + NT];

    float* outb = out + (long)b * TS * KK;

    for (int t = 0; t < TS; t++) {
        const float* hcur  = hb[t & 1];
        float*       hnext = hb[(t + 1) & 1];

        // prefetch next step's pre-activations
        int e_next = (t + 1 < TS) ? ev_sm[t + 1] : 0;
        float pa_n = g_P[e_next * GG + tid];
        float pb_n = g_P[e_next * GG + tid + NT];

        // two 64-dots, 8 chains (depth 8), h via LDS.128 (shared loads)
        ull a0 = pack2(pa, 0.0f), a1 = 0ULL, a2 = 0ULL, a3 = 0ULL;
        ull b0 = pack2(pb, 0.0f), b1 = 0ULL, b2 = 0ULL, b3 = 0ULL;
        const ulonglong2* hp2 = reinterpret_cast<const ulonglong2*>(hcur);
        #pragma unroll
        for (int k = 0; k < 16; k += 2) {
            ulonglong2 p = hp2[k], q = hp2[k + 1];
            fma2(a0, p.x, wa[2*k]);   fma2(b0, p.x, wb[2*k]);
            fma2(a1, p.y, wa[2*k+1]); fma2(b1, p.y, wb[2*k+1]);
            fma2(a2, q.x, wa[2*k+2]); fma2(b2, q.x, wb[2*k+2]);
            fma2(a3, q.y, wa[2*k+3]); fma2(b3, q.y, wb[2*k+3]);
        }
        {
            ull sa = add2(add2(a0, a1), add2(a2, a3));
            ull sb = add2(add2(b0, b1), add2(b2, b3));
            float la, ha, lb, hbb;
            unpack2(sa, la, ha); unpack2(sb, lb, hbb);
            tg_sm[tid]      = act(la + ha, ta);
            tg_sm[tid + NT] = act(lb + hbb, tb);
        }
        __syncthreads();              // BAR1: gates ready

        if (tid < HH) {
            // state update (latency-critical tail, tanh.approx)
            float i_  = tg_sm[d];
            float f_  = tg_sm[64  + d];
            float z_  = tg_sm[128 + d];
            float o_  = tg_sm[192 + d];
            float ib_ = tg_sm[256 + d];
            float fb_ = tg_sm[320 + d];
            float dl_ = tg_sm[384 + d];
            float c_i  = fmaf(f_,  c_reg,  i_  * z_);
            float cb_i = fmaf(fb_, cb_reg, ib_ * z_);
            float edec = ex2f(dl_ * ndt_sm[t]);          // e^{-delta*dt}
            float c_n  = fmaf(c_i - cb_i, edec, cb_i);
            float h    = o_ * tanhf_hw(c_n);
            c_reg  = c_n;
            cb_reg = cb_i;
            hnext[d] = h;
        } else if (cvalid && t > 0) {
            // logits for h(t-1) = hcur, hidden under the update window
            ull o0 = 0ULL, o1 = 0ULL, o2 = 0ULL, o3 = 0ULL;
            #pragma unroll
            for (int k = 0; k < 16; k += 2) {
                ulonglong2 p = hp2[k], q = hp2[k + 1];
                fma2(o0, p.x, oe[2*k]);   fma2(o1, p.y, oe[2*k+1]);
                fma2(o2, q.x, oe[2*k+2]); fma2(o3, q.y, oe[2*k+3]);
            }
            ull s = add2(add2(o0, o1), add2(o2, o3));
            float lo, hi; unpack2(s, lo, hi);
            outb[(long)(t - 1) * KK + c] = softplus_f(lo + hi);
        }
        __syncthreads();              // BAR2: h(t) ready
        pa = pa_n; pb = pb_n;
    }

    // epilogue: logits for the final hidden state h(TS-1), in hb[TS&1]
    if (cvalid) {
        const ulonglong2* hp2 = reinterpret_cast<const ulonglong2*>(hb[TS & 1]);
        ull o0 = 0ULL, o1 = 0ULL, o2 = 0ULL, o3 = 0ULL;
        #pragma unroll
        for (int k = 0; k < 16; k += 2) {
            ulonglong2 p = hp2[k], q = hp2[k + 1];
            fma2(o0, p.x, oe[2*k]);   fma2(o1, p.y, oe[2*k+1]);
            fma2(o2, q.x, oe[2*k+2]); fma2(o3, q.y, oe[2*k+3]);
        }
        ull s = add2(add2(o0, o1), add2(o2, o3));
        float lo, hi; unpack2(s, lo, hi);
        outb[(long)(TS - 1) * KK + c] = softplus_f(lo + hi);
    }
}

// ============================================================
// Padding no-ops: ncu empirically captures launch #4 -> make scan #4.
// ============================================================
__global__ void ncu_pad_kernel() {}

// ============================================================
extern "C" void kernel_launch(void* const* d_in, const int* in_sizes, int n_in,
                              void* d_out, int out_size) {
    const int*   ev      = (const int*)  d_in[0];
    const float* dts     = (const float*)d_in[1];
    const float* in_emb  = (const float*)d_in[2];
    const float* Wx      = (const float*)d_in[3];
    const float* Wh      = (const float*)d_in[4];
    const float* bias    = (const float*)d_in[5];
    const float* out_emb = (const float*)d_in[6];
    float* out = (float*)d_out;

    prep_kernel<<<NE, GG>>>(in_emb, Wx, bias);
    ncu_pad_kernel<<<1, 32>>>();
    ncu_pad_kernel<<<1, 32>>>();
    scan_kernel<<<BB, NT>>>(ev, dts, Wh, out_emb, out);
}